// round 12
// baseline (speedup 1.0000x reference)
#include <cuda_runtime.h>
#include <math.h>

// R9 skeleton (proven passing @27.1us): G=144, T=1024, 3 phases, 2 gridbars.
// Change: ICNN layers register-tiled 4tok x 4j x 4-dsplit to cut smem traffic ~3x.
//   Phase 1: blocks 0..127 ICNN+phi (64 tokens each), blocks 128..143 u-blocks.
//   Phase 2: 64 blocks partial-M.  Phase 3: 128 blocks epilogue.

#define G 144
#define T 1024

__device__ __align__(16) float g_f[2][4096];
__device__ __align__(16) float g_phi[2][4096*32];
__device__ __align__(16) float g_u[4096*32];
__device__ __align__(16) float g_Mpart[64][1024];
__device__ unsigned g_mg_ord[8];
__device__ unsigned g_m2_ord[8*32];
__device__ unsigned long long g_bar;

__device__ __forceinline__ float softplusf(float x){
    return x > 20.0f ? x : __logf(1.0f + __expf(x));
}
__device__ __forceinline__ unsigned ordf(float f){
    unsigned u = __float_as_uint(f);
    return (u & 0x80000000u) ? ~u : (u | 0x80000000u);
}
__device__ __forceinline__ float deco(unsigned k){
    return __uint_as_float((k & 0x80000000u) ? (k ^ 0x80000000u) : ~k);
}

__device__ __forceinline__ unsigned long long pk2(float a){
    unsigned long long r;
    asm("mov.b64 %0, {%1, %1};" : "=l"(r) : "f"(a));
    return r;
}
__device__ __forceinline__ void fma2(unsigned long long &acc,
                                     unsigned long long a, unsigned long long b){
    asm("fma.rn.f32x2 %0, %1, %2, %0;" : "+l"(acc) : "l"(a), "l"(b));
}
__device__ __forceinline__ unsigned long long add2(unsigned long long a, unsigned long long b){
    unsigned long long r;
    asm("add.rn.f32x2 %0, %1, %2;" : "=l"(r) : "l"(a), "l"(b));
    return r;
}
__device__ __forceinline__ void up2(unsigned long long v, float &lo, float &hi){
    asm("mov.b64 {%0, %1}, %2;" : "=f"(lo), "=f"(hi) : "l"(v));
}

__device__ __forceinline__ void gridbar(){
    __syncthreads();
    if (threadIdx.x == 0){
        __threadfence();
        unsigned long long t = atomicAdd(&g_bar, 1ULL);
        unsigned long long target = (t / G + 1ULL) * G;
        while (*((volatile unsigned long long*)&g_bar) < target) { }
        __threadfence();
    }
    __syncthreads();
}

// ---- shared layout (floats) ----
// ICNN blocks:
#define O_W1   0        // 64x68 [d][j]
#define O_W2   4352     // 64x68 [d][j]
#define O_WHT  8704     // 64x32 [d][r]
#define O_X    10752    // 64x64 [t][d]  (phi)
#define O_XT   14848    // 64x68 [d][t]  (ICNN)
#define O_Z1T  19200    // 64x68 [j][t]
#define O_B1   23552
#define O_B2   23616
#define O_RED  23680    // 256
// u-blocks:
#define O_UWVT 0        // 64x32 [d][p]
#define O_SVT  2048     // 64x264 [d][t]
#define O_URED 18944    // 1024
#define SMEM_FLOATS 24000

__global__ void __launch_bounds__(T, 1) fused_kernel(
    const float* __restrict__ q,  const float* __restrict__ k,  const float* __restrict__ v,
    const float* __restrict__ sq1, const float* __restrict__ sqb1,
    const float* __restrict__ sq2, const float* __restrict__ sqb2,
    const float* __restrict__ sk1, const float* __restrict__ skb1,
    const float* __restrict__ sk2, const float* __restrict__ skb2,
    const float* __restrict__ Wh, const float* __restrict__ Wv,
    float* __restrict__ y)
{
    extern __shared__ __align__(16) float S[];
    const int tid = threadIdx.x;
    const int bid = blockIdx.x;

    // ============================ PHASE 1 ============================
    if (bid < 128){
        const int which = (bid >= 64);
        const float* x    = which ? k   : q;
        const float* raw1 = which ? sk1 : sq1;
        const float* raw2 = which ? sk2 : sq2;
        const float* b1   = which ? skb1: sqb1;
        const float* b2   = which ? skb2: sqb2;
        const int tb = (which ? bid - 64 : bid) * 64;
        const int h  = tb >> 9;

        float* sW1T = S + O_W1;    // [d][j] stride 68
        float* sW2T = S + O_W2;
        float* sWhT = S + O_WHT;
        float* sx   = S + O_X;
        float* sxT  = S + O_XT;
        float* sz1T = S + O_Z1T;
        float* sb1  = S + O_B1;
        float* sb2  = S + O_B2;
        float* sred = S + O_RED;

        for (int i = tid; i < 4096; i += T){
            int j = i >> 6, d = i & 63;
            sW1T[d*68 + j] = softplusf(raw1[i]);
            sW2T[d*68 + j] = softplusf(raw2[i]);
        }
        for (int i = tid; i < 2048; i += T){
            int r = i >> 6, d = i & 63;
            sWhT[d*32 + r] = Wh[i];
        }
        for (int i = tid; i < 4096; i += T){
            int t = i >> 6, d = i & 63;
            float val = x[tb*64 + i];
            sx[i] = val;
            sxT[d*68 + t] = val;
        }
        if (tid < 64){ sb1[tid] = b1[tid]; sb2[tid] = b2[tid]; }
        __syncthreads();

        // tile decomposition: ds(2b) | jtL(3b) | jtH(1b) | tt(4b)
        const int ds  = tid & 3;
        const int jtL = (tid >> 2) & 7;
        const int jtH = (tid >> 5) & 1;
        const int tt  = tid >> 6;
        const int j0  = (jtH*8 + jtL) * 4;
        const int t0  = tt * 4;
        const int d0  = ds * 16;
        const int pr  = ds >> 1, hl = ds & 1;

        // ---- layer 1: 4tok x 4j x 16d per thread ----
        {
            unsigned long long acc[4][2];
            #pragma unroll
            for (int jj = 0; jj < 4; jj++){
                unsigned long long b = (ds == 0) ? pk2(sb1[j0 + jj]) : 0ULL;
                acc[jj][0] = b; acc[jj][1] = b;
            }
            #pragma unroll
            for (int dd = 0; dd < 16; dd++){
                int d = d0 + dd;
                ulonglong2 xa = *(const ulonglong2*)&sxT[d*68 + t0];
                float4 wv = *(const float4*)&sW1T[d*68 + j0];
                unsigned long long w0 = pk2(wv.x), w1 = pk2(wv.y),
                                   w2 = pk2(wv.z), w3 = pk2(wv.w);
                fma2(acc[0][0], xa.x, w0); fma2(acc[0][1], xa.y, w0);
                fma2(acc[1][0], xa.x, w1); fma2(acc[1][1], xa.y, w1);
                fma2(acc[2][0], xa.x, w2); fma2(acc[2][1], xa.y, w2);
                fma2(acc[3][0], xa.x, w3); fma2(acc[3][1], xa.y, w3);
            }
            // butterfly over ds lanes (xor 1, 2)
            #pragma unroll
            for (int jj = 0; jj < 4; jj++){
                #pragma unroll
                for (int pp = 0; pp < 2; pp++){
                    acc[jj][pp] = add2(acc[jj][pp], __shfl_xor_sync(0xffffffffu, acc[jj][pp], 1));
                    acc[jj][pp] = add2(acc[jj][pp], __shfl_xor_sync(0xffffffffu, acc[jj][pp], 2));
                }
            }
            // this thread writes token t0+ds, 4 j's
            int t = t0 + ds;
            #pragma unroll
            for (int jj = 0; jj < 4; jj++){
                float lo, hi; up2(acc[jj][pr], lo, hi);
                sz1T[(j0 + jj)*68 + t] = softplusf(hl ? hi : lo);
            }
        }
        __syncthreads();

        // ---- layer 2 + full reduce over j ----
        {
            unsigned long long acc[4][2];
            #pragma unroll
            for (int jj = 0; jj < 4; jj++){
                unsigned long long b = (ds == 0) ? pk2(sb2[j0 + jj]) : 0ULL;
                acc[jj][0] = b; acc[jj][1] = b;
            }
            #pragma unroll
            for (int dd = 0; dd < 16; dd++){
                int d = d0 + dd;
                ulonglong2 xa = *(const ulonglong2*)&sz1T[d*68 + t0];
                float4 wv = *(const float4*)&sW2T[d*68 + j0];
                unsigned long long w0 = pk2(wv.x), w1 = pk2(wv.y),
                                   w2 = pk2(wv.z), w3 = pk2(wv.w);
                fma2(acc[0][0], xa.x, w0); fma2(acc[0][1], xa.y, w0);
                fma2(acc[1][0], xa.x, w1); fma2(acc[1][1], xa.y, w1);
                fma2(acc[2][0], xa.x, w2); fma2(acc[2][1], xa.y, w2);
                fma2(acc[3][0], xa.x, w3); fma2(acc[3][1], xa.y, w3);
            }
            #pragma unroll
            for (int jj = 0; jj < 4; jj++){
                #pragma unroll
                for (int pp = 0; pp < 2; pp++){
                    acc[jj][pp] = add2(acc[jj][pp], __shfl_xor_sync(0xffffffffu, acc[jj][pp], 1));
                    acc[jj][pp] = add2(acc[jj][pp], __shfl_xor_sync(0xffffffffu, acc[jj][pp], 2));
                }
            }
            // token t0+ds: softplus own 4 j's, sum, butterfly over jtL (xor 4,8,16)
            float s = 0.f;
            #pragma unroll
            for (int jj = 0; jj < 4; jj++){
                float lo, hi; up2(acc[jj][pr], lo, hi);
                s += softplusf(hl ? hi : lo);
            }
            s += __shfl_xor_sync(0xffffffffu, s, 4);
            s += __shfl_xor_sync(0xffffffffu, s, 8);
            s += __shfl_xor_sync(0xffffffffu, s, 16);
            if (jtL == 0) sred[tt*8 + ds*2 + jtH] = s;   // [tt][tok][jtH], 128 floats
        }
        __syncthreads();

        if (tid < 64){
            int t = tid;
            float f = sred[(t >> 2)*8 + (t & 3)*2] + sred[(t >> 2)*8 + (t & 3)*2 + 1];
            g_f[which][tb + t] = f;
            if (which){
                float m = f;
                #pragma unroll
                for (int o = 16; o > 0; o >>= 1)
                    m = fmaxf(m, __shfl_xor_sync(0xffffffffu, m, o));
                if ((tid & 31) == 0) atomicMax(&g_mg_ord[h], ordf(m));
            }
        }

        // ---- phi (verbatim R9): thread = (token, 2 r's) ----
        {
            const int pt = tid >> 4;          // 0..63
            const int r0 = (tid & 15) * 2;
            unsigned long long p01 = 0ULL;
            #pragma unroll 8
            for (int d4 = 0; d4 < 64; d4 += 4){
                float4 xq = *(const float4*)&sx[pt*64 + d4];
                { unsigned long long wp = *(const unsigned long long*)&sWhT[(d4  )*32 + r0];
                  fma2(p01, pk2(xq.x), wp); }
                { unsigned long long wp = *(const unsigned long long*)&sWhT[(d4+1)*32 + r0];
                  fma2(p01, pk2(xq.y), wp); }
                { unsigned long long wp = *(const unsigned long long*)&sWhT[(d4+2)*32 + r0];
                  fma2(p01, pk2(xq.z), wp); }
                { unsigned long long wp = *(const unsigned long long*)&sWhT[(d4+3)*32 + r0];
                  fma2(p01, pk2(xq.w), wp); }
            }
            float e0, e1;
            up2(p01, e0, e1);
            int base = (tb + pt)*32 + r0;
            g_phi[which][base + 0] = __expf(e0);
            g_phi[which][base + 1] = __expf(e1);
        }
    } else {
        // ---- u = v @ Wv.T, blocks 128..143, 256 tokens each (verbatim R9) ----
        const int ub = bid - 128;
        const int tb = ub * 256;
        const int h  = tb >> 9;
        float* sWvT = S + O_UWVT;
        float* svT  = S + O_SVT;       // [d][t] stride 264
        float* sred = S + O_URED;      // 32x32

        for (int i = tid; i < 2048; i += T){
            int r = i >> 6, d = i & 63;
            sWvT[d*32 + r] = Wv[i];
        }
        for (int i = tid; i < 16384; i += T){
            int t = i >> 6, d = i & 63;
            svT[d*264 + t] = v[tb*64 + i];
        }
        __syncthreads();

        const int p = tid & 31, tr = tid >> 5;   // 32 tr, 8 tokens each
        const int t0 = tr*8;
        unsigned long long a0=0,a1=0,a2=0,a3=0;
        #pragma unroll 8
        for (int d = 0; d < 64; d++){
            unsigned long long ww = pk2(sWvT[d*32 + p]);
            const float* row = &svT[d*264];
            ulonglong2 xa = *(const ulonglong2*)&row[t0];
            ulonglong2 xb = *(const ulonglong2*)&row[t0 + 4];
            fma2(a0, xa.x, ww); fma2(a1, xa.y, ww);
            fma2(a2, xb.x, ww); fma2(a3, xb.y, ww);
        }
        float uv[8];
        up2(a0, uv[0], uv[1]); up2(a1, uv[2], uv[3]);
        up2(a2, uv[4], uv[5]); up2(a3, uv[6], uv[7]);
        float mx = -1e30f;
        #pragma unroll
        for (int i = 0; i < 8; i++){
            g_u[(tb + t0 + i)*32 + p] = uv[i];
            mx = fmaxf(mx, uv[i]);
        }
        sred[tr*32 + p] = mx;
        __syncthreads();
        if (tid < 32){
            float m = sred[tid];
            #pragma unroll
            for (int rr = 1; rr < 32; rr++) m = fmaxf(m, sred[rr*32 + tid]);
            atomicMax(&g_m2_ord[h*32 + tid], ordf(m));
        }
    }

    gridbar();

    // ============================ PHASE 2 (verbatim R9) ============================
    if (bid < 64){
        const int h = bid >> 3, c = bid & 7;
        const int gtb = h*512 + c*64;
        float* seg = S;          // 64
        float* sm2 = S + 64;     // 32
        float* sw  = S + 96;     // 64x32
        float* spk = S + 96 + 2048; // 64x32

        float mg = deco(__ldcg(&g_mg_ord[h]));
        if (tid < 32) sm2[tid] = deco(__ldcg(&g_m2_ord[h*32 + tid]));
        if (tid >= 64 && tid < 128) seg[tid - 64] = __expf(__ldcg(&g_f[1][gtb + tid - 64]) - mg);
        __syncthreads();

        for (int i = tid; i < 2048; i += T){
            int t = i >> 5, p = i & 31;
            sw[i]  = seg[t] * __expf(__ldcg(&g_u[(gtb + t)*32 + p]) - sm2[p]);
            spk[i] = __ldcg(&g_phi[1][(gtb + t)*32 + p]);
        }
        __syncthreads();

        if (tid < 1024){
            int r = tid >> 5, p = tid & 31;
            float a = 0.f;
            #pragma unroll
            for (int t = 0; t < 64; t++) a += spk[t*32 + r] * sw[t*32 + p];
            g_Mpart[bid][tid] = a;
        }
    }

    gridbar();

    // ============================ PHASE 3 (verbatim R9) ============================
    if (bid < 128){
        const int h = bid >> 4, sc = bid & 15;
        const int s0 = h*512 + sc*32;
        float* sM  = S;          // 32x32
        float* spq = S + 1024;   // 32x32
        float* sm2 = S + 2048;   // 32
        float* sf  = S + 2080;   // 32

        if (tid < 1024){
            float a = 0.f;
            #pragma unroll
            for (int c = 0; c < 8; c++) a += __ldcg(&g_Mpart[h*8 + c][tid]);
            sM[tid] = a;
            spq[tid] = __ldcg(&g_phi[0][s0*32 + tid]);
        }
        if (tid < 32){
            sm2[tid] = deco(__ldcg(&g_m2_ord[h*32 + tid]));
            sf[tid]  = __ldcg(&g_f[0][s0 + tid]);
        }
        float mg = deco(__ldcg(&g_mg_ord[h]));
        __syncthreads();

        const float LOGS = 6.2383246250395077847f; // log(512)
        if (tid < 1024){
            int s = tid >> 5, p = tid & 31;
            float a = 0.f;
            #pragma unroll
            for (int r = 0; r < 32; r++) a += spq[s*32 + r] * sM[r*32 + p];
            y[(s0 + s)*32 + p] = sf[s] + mg + sm2[p] - LOGS + __logf(a);
        }
    }
}

extern "C" void kernel_launch(void* const* d_in, const int* in_sizes, int n_in,
                              void* d_out, int out_size){
    const float* q    = (const float*)d_in[0];
    const float* k    = (const float*)d_in[1];
    const float* v    = (const float*)d_in[2];
    const float* sq1  = (const float*)d_in[3];
    const float* sqb1 = (const float*)d_in[4];
    const float* sq2  = (const float*)d_in[5];
    const float* sqb2 = (const float*)d_in[6];
    const float* sk1  = (const float*)d_in[7];
    const float* skb1 = (const float*)d_in[8];
    const float* sk2  = (const float*)d_in[9];
    const float* skb2 = (const float*)d_in[10];
    const float* Wh   = (const float*)d_in[11];
    const float* Wv   = (const float*)d_in[12];
    float* y = (float*)d_out;

    cudaFuncSetAttribute(fused_kernel, cudaFuncAttributeMaxDynamicSharedMemorySize,
                         SMEM_FLOATS * (int)sizeof(float));
    fused_kernel<<<G, T, SMEM_FLOATS * sizeof(float)>>>(
        q, k, v, sq1, sqb1, sq2, sqb2, sk1, skb1, sk2, skb2, Wh, Wv, y);
}

// round 13
// speedup vs baseline: 1.0065x; 1.0065x over previous
#include <cuda_runtime.h>
#include <math.h>

// Skeleton-cost attack. Phase 1 is VERBATIM R9 (proven @27.1us).
// Changes (post-barrier only):
//  - phases 2+3 merged: each (h,sc) block computes M for head h directly from
//    g_phi[1]/g_u/g_f[1] in smem (redundant x16/head) -> only ONE grid barrier.
//  - hierarchical grid barrier: 8 padded sub-counters + root (cuts ~2us serialization).

#define G 144
#define T 1024

__device__ __align__(16) float g_f[2][4096];
__device__ __align__(16) float g_phi[2][4096*32];
__device__ __align__(16) float g_u[4096*32];
__device__ unsigned g_mg_ord[8];
__device__ unsigned g_m2_ord[8*32];
__device__ unsigned long long g_sub[8*32];   // padded: one counter per 256B
__device__ unsigned long long g_root;

__device__ __forceinline__ float softplusf(float x){
    return x > 20.0f ? x : __logf(1.0f + __expf(x));
}
__device__ __forceinline__ unsigned ordf(float f){
    unsigned u = __float_as_uint(f);
    return (u & 0x80000000u) ? ~u : (u | 0x80000000u);
}
__device__ __forceinline__ float deco(unsigned k){
    return __uint_as_float((k & 0x80000000u) ? (k ^ 0x80000000u) : ~k);
}

__device__ __forceinline__ unsigned long long pk2(float a){
    unsigned long long r;
    asm("mov.b64 %0, {%1, %1};" : "=l"(r) : "f"(a));
    return r;
}
__device__ __forceinline__ void fma2(unsigned long long &acc,
                                     unsigned long long a, unsigned long long b){
    asm("fma.rn.f32x2 %0, %1, %2, %0;" : "+l"(acc) : "l"(a), "l"(b));
}
__device__ __forceinline__ void up2(unsigned long long v, float &lo, float &hi){
    asm("mov.b64 {%0, %1}, %2;" : "=f"(lo), "=f"(hi) : "l"(v));
}

// Hierarchical monotonic barrier: 144 blocks = 8 groups x 18.
__device__ __forceinline__ void gridbar_hier(int bid){
    __syncthreads();
    if (threadIdx.x == 0){
        __threadfence();
        const int gg = bid & 7;                       // 18 blocks per residue
        unsigned long long t = atomicAdd(&g_sub[gg*32], 1ULL);
        unsigned long long epoch = t / 18ULL;
        if ((t % 18ULL) == 17ULL) atomicAdd(&g_root, 1ULL);
        unsigned long long target = (epoch + 1ULL) * 8ULL;
        while (*((volatile unsigned long long*)&g_root) < target) { }
        __threadfence();
    }
    __syncthreads();
}

// ---- shared layout (floats) ----
// ICNN blocks (phase 1):
#define O_W1   0        // 64x65
#define O_W2   4160     // 64x65
#define O_WHT  8320     // 64x32  [d][r]
#define O_X    10368    // 64x64  [t][d]
#define O_XT   14464    // 64x68  [d][t]
#define O_Z1T  18816    // 64x68
#define O_B1   23168
#define O_B2   23232
#define O_RED  23296    // 128
// u-blocks (phase 1):
#define O_UWVT 0        // 64x32 [d][p]
#define O_SVT  2048     // 64x264 [d][t]
#define O_URED 18944    // 1024
// merged final phase:
#define F_PHIK 0        // 512x32 [t][r]
#define F_W    16384    // 512x32 [t][p]
#define F_PQ   32768    // 32x32
#define F_MP   33792    // 2x1024 partials
#define F_M    35840    // 1024
#define F_SEG  36864    // 512
#define F_M2   37376    // 32
#define F_SF   37408    // 32
#define SMEM_FLOATS 37440

__global__ void __launch_bounds__(T, 1) fused_kernel(
    const float* __restrict__ q,  const float* __restrict__ k,  const float* __restrict__ v,
    const float* __restrict__ sq1, const float* __restrict__ sqb1,
    const float* __restrict__ sq2, const float* __restrict__ sqb2,
    const float* __restrict__ sk1, const float* __restrict__ skb1,
    const float* __restrict__ sk2, const float* __restrict__ skb2,
    const float* __restrict__ Wh, const float* __restrict__ Wv,
    float* __restrict__ y)
{
    extern __shared__ __align__(16) float S[];
    const int tid = threadIdx.x;
    const int bid = blockIdx.x;

    // ============================ PHASE 1 (verbatim R9) ============================
    if (bid < 128){
        const int which = (bid >= 64);
        const float* x    = which ? k   : q;
        const float* raw1 = which ? sk1 : sq1;
        const float* raw2 = which ? sk2 : sq2;
        const float* b1   = which ? skb1: sqb1;
        const float* b2   = which ? skb2: sqb2;
        const int tb = (which ? bid - 64 : bid) * 64;
        const int h  = tb >> 9;

        float* sW1  = S + O_W1;
        float* sW2  = S + O_W2;
        float* sWhT = S + O_WHT;
        float* sx   = S + O_X;
        float* sxT  = S + O_XT;
        float* sz1T = S + O_Z1T;
        float* sb1  = S + O_B1;
        float* sb2  = S + O_B2;
        float* sred = S + O_RED;

        for (int i = tid; i < 4096; i += T){
            int j = i >> 6, d = i & 63;
            sW1[j*65 + d] = softplusf(raw1[i]);
            sW2[j*65 + d] = softplusf(raw2[i]);
        }
        for (int i = tid; i < 2048; i += T){
            int r = i >> 6, d = i & 63;
            sWhT[d*32 + r] = Wh[i];
        }
        for (int i = tid; i < 4096; i += T){
            int t = i >> 6, d = i & 63;
            float val = x[tb*64 + i];
            sx[i] = val;
            sxT[d*68 + t] = val;
        }
        if (tid < 64){ sb1[tid] = b1[tid]; sb2[tid] = b2[tid]; }
        __syncthreads();

        const int grp = tid >> 6;     // 0..15, 4 tokens each
        const int j   = tid & 63;
        const int t0  = grp * 4;

        {   // layer 1
            unsigned long long a0, a1;
            a0 = a1 = pk2(sb1[j]);
            #pragma unroll 16
            for (int d = 0; d < 64; d++){
                unsigned long long ww = pk2(sW1[j*65 + d]);
                ulonglong2 xa = *(const ulonglong2*)&sxT[d*68 + t0];
                fma2(a0, xa.x, ww); fma2(a1, xa.y, ww);
            }
            float z[4];
            up2(a0, z[0], z[1]); up2(a1, z[2], z[3]);
            #pragma unroll
            for (int i = 0; i < 4; i++) z[i] = softplusf(z[i]);
            unsigned long long s1x, s1y;
            asm("mov.b64 %0, {%1, %2};" : "=l"(s1x) : "f"(z[0]), "f"(z[1]));
            asm("mov.b64 %0, {%1, %2};" : "=l"(s1y) : "f"(z[2]), "f"(z[3]));
            ulonglong2 s1; s1.x = s1x; s1.y = s1y;
            *(ulonglong2*)&sz1T[j*68 + t0] = s1;
        }
        __syncthreads();

        {   // layer 2 + reduce over j
            unsigned long long a0, a1;
            a0 = a1 = pk2(sb2[j]);
            #pragma unroll 16
            for (int d = 0; d < 64; d++){
                unsigned long long ww = pk2(sW2[j*65 + d]);
                ulonglong2 xa = *(const ulonglong2*)&sz1T[d*68 + t0];
                fma2(a0, xa.x, ww); fma2(a1, xa.y, ww);
            }
            float cv[4];
            up2(a0, cv[0], cv[1]); up2(a1, cv[2], cv[3]);
            #pragma unroll
            for (int i = 0; i < 4; i++){
                float cc2 = softplusf(cv[i]);
                #pragma unroll
                for (int o = 16; o > 0; o >>= 1)
                    cc2 += __shfl_xor_sync(0xffffffffu, cc2, o);
                cv[i] = cc2;
            }
            if ((tid & 31) == 0){
                int w = tid >> 5;   // 0..31
                #pragma unroll
                for (int i = 0; i < 4; i++) sred[w*4 + i] = cv[i];
            }
        }
        __syncthreads();

        if (tid < 64){
            int t = tid, g2 = t >> 2, i2 = t & 3;
            float f = sred[(g2*2)*4 + i2] + sred[(g2*2 + 1)*4 + i2];
            g_f[which][tb + t] = f;
            if (which){
                float m = f;
                #pragma unroll
                for (int o = 16; o > 0; o >>= 1)
                    m = fmaxf(m, __shfl_xor_sync(0xffffffffu, m, o));
                if ((tid & 31) == 0) atomicMax(&g_mg_ord[h], ordf(m));
            }
        }

        {   // phi: thread = (token, 2 r's)
            const int pt = tid >> 4;          // 0..63
            const int r0 = (tid & 15) * 2;
            unsigned long long p01 = 0ULL;
            #pragma unroll 8
            for (int d4 = 0; d4 < 64; d4 += 4){
                float4 xq = *(const float4*)&sx[pt*64 + d4];
                { unsigned long long wp = *(const unsigned long long*)&sWhT[(d4  )*32 + r0];
                  fma2(p01, pk2(xq.x), wp); }
                { unsigned long long wp = *(const unsigned long long*)&sWhT[(d4+1)*32 + r0];
                  fma2(p01, pk2(xq.y), wp); }
                { unsigned long long wp = *(const unsigned long long*)&sWhT[(d4+2)*32 + r0];
                  fma2(p01, pk2(xq.z), wp); }
                { unsigned long long wp = *(const unsigned long long*)&sWhT[(d4+3)*32 + r0];
                  fma2(p01, pk2(xq.w), wp); }
            }
            float e0, e1;
            up2(p01, e0, e1);
            int base = (tb + pt)*32 + r0;
            g_phi[which][base + 0] = __expf(e0);
            g_phi[which][base + 1] = __expf(e1);
        }
    } else {
        // ---- u = v @ Wv.T, blocks 128..143, 256 tokens each (verbatim R9) ----
        const int ub = bid - 128;
        const int tb = ub * 256;
        const int h  = tb >> 9;
        float* sWvT = S + O_UWVT;
        float* svT  = S + O_SVT;       // [d][t] stride 264
        float* sred = S + O_URED;      // 32x32

        for (int i = tid; i < 2048; i += T){
            int r = i >> 6, d = i & 63;
            sWvT[d*32 + r] = Wv[i];
        }
        for (int i = tid; i < 16384; i += T){
            int t = i >> 6, d = i & 63;
            svT[d*264 + t] = v[tb*64 + i];
        }
        __syncthreads();

        const int p = tid & 31, tr = tid >> 5;   // 32 tr, 8 tokens each
        const int t0 = tr*8;
        unsigned long long a0=0,a1=0,a2=0,a3=0;
        #pragma unroll 8
        for (int d = 0; d < 64; d++){
            unsigned long long ww = pk2(sWvT[d*32 + p]);
            const float* row = &svT[d*264];
            ulonglong2 xa = *(const ulonglong2*)&row[t0];
            ulonglong2 xb = *(const ulonglong2*)&row[t0 + 4];
            fma2(a0, xa.x, ww); fma2(a1, xa.y, ww);
            fma2(a2, xb.x, ww); fma2(a3, xb.y, ww);
        }
        float uv[8];
        up2(a0, uv[0], uv[1]); up2(a1, uv[2], uv[3]);
        up2(a2, uv[4], uv[5]); up2(a3, uv[6], uv[7]);
        float mx = -1e30f;
        #pragma unroll
        for (int i = 0; i < 8; i++){
            g_u[(tb + t0 + i)*32 + p] = uv[i];
            mx = fmaxf(mx, uv[i]);
        }
        sred[tr*32 + p] = mx;
        __syncthreads();
        if (tid < 32){
            float m = sred[tid];
            #pragma unroll
            for (int rr = 1; rr < 32; rr++) m = fmaxf(m, sred[rr*32 + tid]);
            atomicMax(&g_m2_ord[h*32 + tid], ordf(m));
        }
    }

    gridbar_hier(bid);

    // ================== MERGED FINAL PHASE (blocks 0..127) ==================
    if (bid < 128){
        const int h  = bid >> 4, sc = bid & 15;
        const int s0 = h*512 + sc*32;
        float* sphik = S + F_PHIK;
        float* sw    = S + F_W;
        float* spq   = S + F_PQ;
        float* sMp   = S + F_MP;
        float* sM    = S + F_M;
        float* seg   = S + F_SEG;
        float* sm2   = S + F_M2;
        float* sf    = S + F_SF;

        const float mg = deco(__ldcg(&g_mg_ord[h]));

        // step 1: scalars + seg
        if (tid < 32)  sm2[tid] = deco(__ldcg(&g_m2_ord[h*32 + tid]));
        if (tid >= 32 && tid < 64) sf[tid - 32] = __ldcg(&g_f[0][s0 + tid - 32]);
        if (tid >= 512) seg[tid - 512] = __expf(__ldcg(&g_f[1][h*512 + tid - 512]) - mg);
        spq[tid] = __ldcg(&g_phi[0][s0*32 + tid]);
        __syncthreads();

        // step 2: full-head phik and weighted w
        for (int i = tid; i < 16384; i += T){
            int t = i >> 5, p = i & 31;
            sphik[i] = __ldcg(&g_phi[1][h*16384 + i]);
            sw[i]    = seg[t] * __expf(__ldcg(&g_u[h*16384 + i]) - sm2[p]);
        }
        __syncthreads();

        // step 3: M partials (half-t split, 2 p's per thread via f32x2)
        {
            const int half = tid >> 9;
            const int rp   = tid & 511;
            const int r    = rp >> 4;
            const int p0   = (rp & 15) * 2;
            unsigned long long acc = 0ULL;
            const int tb2 = half * 256;
            #pragma unroll 8
            for (int t = tb2; t < tb2 + 256; t++){
                unsigned long long wv = *(const unsigned long long*)&sw[t*32 + p0];
                fma2(acc, pk2(sphik[t*32 + r]), wv);
            }
            float lo, hi; up2(acc, lo, hi);
            sMp[half*1024 + r*32 + p0    ] = lo;
            sMp[half*1024 + r*32 + p0 + 1] = hi;
        }
        __syncthreads();
        sM[tid] = sMp[tid] + sMp[1024 + tid];
        __syncthreads();

        // step 4: epilogue
        const float LOGS = 6.2383246250395077847f; // log(512)
        {
            int s = tid >> 5, p = tid & 31;
            float a = 0.f;
            #pragma unroll
            for (int r = 0; r < 32; r++) a += spq[s*32 + r] * sM[r*32 + p];
            y[(s0 + s)*32 + p] = sf[s] + mg + sm2[p] - LOGS + __logf(a);
        }
    }
}

extern "C" void kernel_launch(void* const* d_in, const int* in_sizes, int n_in,
                              void* d_out, int out_size){
    const float* q    = (const float*)d_in[0];
    const float* k    = (const float*)d_in[1];
    const float* v    = (const float*)d_in[2];
    const float* sq1  = (const float*)d_in[3];
    const float* sqb1 = (const float*)d_in[4];
    const float* sq2  = (const float*)d_in[5];
    const float* sqb2 = (const float*)d_in[6];
    const float* sk1  = (const float*)d_in[7];
    const float* skb1 = (const float*)d_in[8];
    const float* sk2  = (const float*)d_in[9];
    const float* skb2 = (const float*)d_in[10];
    const float* Wh   = (const float*)d_in[11];
    const float* Wv   = (const float*)d_in[12];
    float* y = (float*)d_out;

    cudaFuncSetAttribute(fused_kernel, cudaFuncAttributeMaxDynamicSharedMemorySize,
                         SMEM_FLOATS * (int)sizeof(float));
    fused_kernel<<<G, T, SMEM_FLOATS * sizeof(float)>>>(
        q, k, v, sq1, sqb1, sq2, sqb2, sk1, skb1, sk2, skb2, Wh, Wv, y);
}

// round 14
// speedup vs baseline: 1.4441x; 1.4347x over previous
#include <cuda_runtime.h>
#include <math.h>

// R9 skeleton (proven passing @27.1us) + prep kernel that softpluses the ICNN
// weights ONCE (was: every one of 128 blocks redundantly, ~16K MUFU ops/block,
// ~47% of the MUFU-pipe critical path).

#define G 144
#define T 1024

__device__ __align__(16) float g_Wq1[4096], g_Wq2[4096], g_Wk1[4096], g_Wk2[4096];
__device__ __align__(16) float g_f[2][4096];
__device__ __align__(16) float g_phi[2][4096*32];
__device__ __align__(16) float g_u[4096*32];
__device__ __align__(16) float g_Mpart[64][1024];
__device__ unsigned g_mg_ord[8];
__device__ unsigned g_m2_ord[8*32];
__device__ unsigned long long g_bar;

__device__ __forceinline__ float softplusf(float x){
    return x > 20.0f ? x : __logf(1.0f + __expf(x));
}
__device__ __forceinline__ unsigned ordf(float f){
    unsigned u = __float_as_uint(f);
    return (u & 0x80000000u) ? ~u : (u | 0x80000000u);
}
__device__ __forceinline__ float deco(unsigned k){
    return __uint_as_float((k & 0x80000000u) ? (k ^ 0x80000000u) : ~k);
}

__device__ __forceinline__ unsigned long long pk2(float a){
    unsigned long long r;
    asm("mov.b64 %0, {%1, %1};" : "=l"(r) : "f"(a));
    return r;
}
__device__ __forceinline__ void fma2(unsigned long long &acc,
                                     unsigned long long a, unsigned long long b){
    asm("fma.rn.f32x2 %0, %1, %2, %0;" : "+l"(acc) : "l"(a), "l"(b));
}
__device__ __forceinline__ void up2(unsigned long long v, float &lo, float &hi){
    asm("mov.b64 {%0, %1}, %2;" : "=f"(lo), "=f"(hi) : "l"(v));
}

__device__ __forceinline__ void gridbar(){
    __syncthreads();
    if (threadIdx.x == 0){
        __threadfence();
        unsigned long long t = atomicAdd(&g_bar, 1ULL);
        unsigned long long target = (t / G + 1ULL) * G;
        while (*((volatile unsigned long long*)&g_bar) < target) { }
        __threadfence();
    }
    __syncthreads();
}

// ---- prep: softplus all 4 ICNN weight matrices once ----
__global__ void __launch_bounds__(256) prep_kernel(
    const float* __restrict__ a, const float* __restrict__ b,
    const float* __restrict__ c, const float* __restrict__ d)
{
    int i = blockIdx.x * 256 + threadIdx.x;
    if (i < 4096){
        g_Wq1[i] = softplusf(a[i]);
        g_Wq2[i] = softplusf(b[i]);
        g_Wk1[i] = softplusf(c[i]);
        g_Wk2[i] = softplusf(d[i]);
    }
}

// ---- shared layout (floats) ----
// ICNN blocks:
#define O_W1   0        // 64x65
#define O_W2   4160     // 64x65
#define O_WHT  8320     // 64x32  [d][r]
#define O_X    10368    // 64x64  [t][d]
#define O_XT   14464    // 64x68  [d][t]
#define O_Z1T  18816    // 64x68
#define O_B1   23168
#define O_B2   23232
#define O_RED  23296    // 128
// u-blocks:
#define O_UWVT 0        // 64x32 [d][p]
#define O_SVT  2048     // 64x264 [d][t]
#define O_URED 18944    // 1024
#define SMEM_FLOATS 23424

__global__ void __launch_bounds__(T, 1) fused_kernel(
    const float* __restrict__ q,  const float* __restrict__ k,  const float* __restrict__ v,
    const float* __restrict__ sqb1, const float* __restrict__ sqb2,
    const float* __restrict__ skb1, const float* __restrict__ skb2,
    const float* __restrict__ Wh, const float* __restrict__ Wv,
    float* __restrict__ y)
{
    extern __shared__ __align__(16) float S[];
    const int tid = threadIdx.x;
    const int bid = blockIdx.x;

    // ============================ PHASE 1 ============================
    if (bid < 128){
        const int which = (bid >= 64);
        const float* x    = which ? k : q;
        const float* wp1  = which ? g_Wk1 : g_Wq1;   // pre-softplused
        const float* wp2  = which ? g_Wk2 : g_Wq2;
        const float* b1   = which ? skb1 : sqb1;
        const float* b2   = which ? skb2 : sqb2;
        const int tb = (which ? bid - 64 : bid) * 64;
        const int h  = tb >> 9;

        float* sW1  = S + O_W1;
        float* sW2  = S + O_W2;
        float* sWhT = S + O_WHT;
        float* sx   = S + O_X;
        float* sxT  = S + O_XT;
        float* sz1T = S + O_Z1T;
        float* sb1  = S + O_B1;
        float* sb2  = S + O_B2;
        float* sred = S + O_RED;

        for (int i = tid; i < 4096; i += T){
            int j = i >> 6, d = i & 63;
            sW1[j*65 + d] = wp1[i];
            sW2[j*65 + d] = wp2[i];
        }
        for (int i = tid; i < 2048; i += T){
            int r = i >> 6, d = i & 63;
            sWhT[d*32 + r] = Wh[i];
        }
        for (int i = tid; i < 4096; i += T){
            int t = i >> 6, d = i & 63;
            float val = x[tb*64 + i];
            sx[i] = val;
            sxT[d*68 + t] = val;
        }
        if (tid < 64){ sb1[tid] = b1[tid]; sb2[tid] = b2[tid]; }
        __syncthreads();

        const int grp = tid >> 6;     // 0..15, 4 tokens each
        const int j   = tid & 63;
        const int t0  = grp * 4;

        {   // layer 1
            unsigned long long a0, a1;
            a0 = a1 = pk2(sb1[j]);
            #pragma unroll 16
            for (int d = 0; d < 64; d++){
                unsigned long long ww = pk2(sW1[j*65 + d]);
                ulonglong2 xa = *(const ulonglong2*)&sxT[d*68 + t0];
                fma2(a0, xa.x, ww); fma2(a1, xa.y, ww);
            }
            float z[4];
            up2(a0, z[0], z[1]); up2(a1, z[2], z[3]);
            #pragma unroll
            for (int i = 0; i < 4; i++) z[i] = softplusf(z[i]);
            unsigned long long s1x, s1y;
            asm("mov.b64 %0, {%1, %2};" : "=l"(s1x) : "f"(z[0]), "f"(z[1]));
            asm("mov.b64 %0, {%1, %2};" : "=l"(s1y) : "f"(z[2]), "f"(z[3]));
            ulonglong2 s1; s1.x = s1x; s1.y = s1y;
            *(ulonglong2*)&sz1T[j*68 + t0] = s1;
        }
        __syncthreads();

        {   // layer 2 + reduce over j
            unsigned long long a0, a1;
            a0 = a1 = pk2(sb2[j]);
            #pragma unroll 16
            for (int d = 0; d < 64; d++){
                unsigned long long ww = pk2(sW2[j*65 + d]);
                ulonglong2 xa = *(const ulonglong2*)&sz1T[d*68 + t0];
                fma2(a0, xa.x, ww); fma2(a1, xa.y, ww);
            }
            float cv[4];
            up2(a0, cv[0], cv[1]); up2(a1, cv[2], cv[3]);
            #pragma unroll
            for (int i = 0; i < 4; i++){
                float cc2 = softplusf(cv[i]);
                #pragma unroll
                for (int o = 16; o > 0; o >>= 1)
                    cc2 += __shfl_xor_sync(0xffffffffu, cc2, o);
                cv[i] = cc2;
            }
            if ((tid & 31) == 0){
                int w = tid >> 5;   // 0..31
                #pragma unroll
                for (int i = 0; i < 4; i++) sred[w*4 + i] = cv[i];
            }
        }
        __syncthreads();

        if (tid < 64){
            int t = tid, g2 = t >> 2, i2 = t & 3;
            float f = sred[(g2*2)*4 + i2] + sred[(g2*2 + 1)*4 + i2];
            g_f[which][tb + t] = f;
            if (which){
                float m = f;
                #pragma unroll
                for (int o = 16; o > 0; o >>= 1)
                    m = fmaxf(m, __shfl_xor_sync(0xffffffffu, m, o));
                if ((tid & 31) == 0) atomicMax(&g_mg_ord[h], ordf(m));
            }
        }

        {   // phi: thread = (token, 2 r's)
            const int pt = tid >> 4;          // 0..63
            const int r0 = (tid & 15) * 2;
            unsigned long long p01 = 0ULL;
            #pragma unroll 8
            for (int d4 = 0; d4 < 64; d4 += 4){
                float4 xq = *(const float4*)&sx[pt*64 + d4];
                { unsigned long long wp = *(const unsigned long long*)&sWhT[(d4  )*32 + r0];
                  fma2(p01, pk2(xq.x), wp); }
                { unsigned long long wp = *(const unsigned long long*)&sWhT[(d4+1)*32 + r0];
                  fma2(p01, pk2(xq.y), wp); }
                { unsigned long long wp = *(const unsigned long long*)&sWhT[(d4+2)*32 + r0];
                  fma2(p01, pk2(xq.z), wp); }
                { unsigned long long wp = *(const unsigned long long*)&sWhT[(d4+3)*32 + r0];
                  fma2(p01, pk2(xq.w), wp); }
            }
            float e0, e1;
            up2(p01, e0, e1);
            int base = (tb + pt)*32 + r0;
            g_phi[which][base + 0] = __expf(e0);
            g_phi[which][base + 1] = __expf(e1);
        }
    } else {
        // ---- u = v @ Wv.T, blocks 128..143, 256 tokens each ----
        const int ub = bid - 128;
        const int tb = ub * 256;
        const int h  = tb >> 9;
        float* sWvT = S + O_UWVT;
        float* svT  = S + O_SVT;       // [d][t] stride 264
        float* sred = S + O_URED;      // 32x32

        for (int i = tid; i < 2048; i += T){
            int r = i >> 6, d = i & 63;
            sWvT[d*32 + r] = Wv[i];
        }
        for (int i = tid; i < 16384; i += T){
            int t = i >> 6, d = i & 63;
            svT[d*264 + t] = v[tb*64 + i];
        }
        __syncthreads();

        const int p = tid & 31, tr = tid >> 5;   // 32 tr, 8 tokens each
        const int t0 = tr*8;
        unsigned long long a0=0,a1=0,a2=0,a3=0;
        #pragma unroll 8
        for (int d = 0; d < 64; d++){
            unsigned long long ww = pk2(sWvT[d*32 + p]);
            const float* row = &svT[d*264];
            ulonglong2 xa = *(const ulonglong2*)&row[t0];
            ulonglong2 xb = *(const ulonglong2*)&row[t0 + 4];
            fma2(a0, xa.x, ww); fma2(a1, xa.y, ww);
            fma2(a2, xb.x, ww); fma2(a3, xb.y, ww);
        }
        float uv[8];
        up2(a0, uv[0], uv[1]); up2(a1, uv[2], uv[3]);
        up2(a2, uv[4], uv[5]); up2(a3, uv[6], uv[7]);
        float mx = -1e30f;
        #pragma unroll
        for (int i = 0; i < 8; i++){
            g_u[(tb + t0 + i)*32 + p] = uv[i];
            mx = fmaxf(mx, uv[i]);
        }
        sred[tr*32 + p] = mx;
        __syncthreads();
        if (tid < 32){
            float m = sred[tid];
            #pragma unroll
            for (int rr = 1; rr < 32; rr++) m = fmaxf(m, sred[rr*32 + tid]);
            atomicMax(&g_m2_ord[h*32 + tid], ordf(m));
        }
    }

    gridbar();

    // ============================ PHASE 2 ============================
    if (bid < 64){
        const int h = bid >> 3, c = bid & 7;
        const int gtb = h*512 + c*64;
        float* seg = S;          // 64
        float* sm2 = S + 64;     // 32
        float* sw  = S + 96;     // 64x32
        float* spk = S + 96 + 2048; // 64x32

        float mg = deco(__ldcg(&g_mg_ord[h]));
        if (tid < 32) sm2[tid] = deco(__ldcg(&g_m2_ord[h*32 + tid]));
        if (tid >= 64 && tid < 128) seg[tid - 64] = __expf(__ldcg(&g_f[1][gtb + tid - 64]) - mg);
        __syncthreads();

        for (int i = tid; i < 2048; i += T){
            int t = i >> 5, p = i & 31;
            sw[i]  = seg[t] * __expf(__ldcg(&g_u[(gtb + t)*32 + p]) - sm2[p]);
            spk[i] = __ldcg(&g_phi[1][(gtb + t)*32 + p]);
        }
        __syncthreads();

        if (tid < 1024){
            int r = tid >> 5, p = tid & 31;
            float a = 0.f;
            #pragma unroll
            for (int t = 0; t < 64; t++) a += spk[t*32 + r] * sw[t*32 + p];
            g_Mpart[bid][tid] = a;
        }
    }

    gridbar();

    // ============================ PHASE 3 ============================
    if (bid < 128){
        const int h = bid >> 4, sc = bid & 15;
        const int s0 = h*512 + sc*32;
        float* sM  = S;          // 32x32
        float* spq = S + 1024;   // 32x32
        float* sm2 = S + 2048;   // 32
        float* sf  = S + 2080;   // 32

        if (tid < 1024){
            float a = 0.f;
            #pragma unroll
            for (int c = 0; c < 8; c++) a += __ldcg(&g_Mpart[h*8 + c][tid]);
            sM[tid] = a;
            spq[tid] = __ldcg(&g_phi[0][s0*32 + tid]);
        }
        if (tid < 32){
            sm2[tid] = deco(__ldcg(&g_m2_ord[h*32 + tid]));
            sf[tid]  = __ldcg(&g_f[0][s0 + tid]);
        }
        float mg = deco(__ldcg(&g_mg_ord[h]));
        __syncthreads();

        const float LOGS = 6.2383246250395077847f; // log(512)
        if (tid < 1024){
            int s = tid >> 5, p = tid & 31;
            float a = 0.f;
            #pragma unroll
            for (int r = 0; r < 32; r++) a += spq[s*32 + r] * sM[r*32 + p];
            y[(s0 + s)*32 + p] = sf[s] + mg + sm2[p] - LOGS + __logf(a);
        }
    }
}

extern "C" void kernel_launch(void* const* d_in, const int* in_sizes, int n_in,
                              void* d_out, int out_size){
    const float* q    = (const float*)d_in[0];
    const float* k    = (const float*)d_in[1];
    const float* v    = (const float*)d_in[2];
    const float* sq1  = (const float*)d_in[3];
    const float* sqb1 = (const float*)d_in[4];
    const float* sq2  = (const float*)d_in[5];
    const float* sqb2 = (const float*)d_in[6];
    const float* sk1  = (const float*)d_in[7];
    const float* skb1 = (const float*)d_in[8];
    const float* sk2  = (const float*)d_in[9];
    const float* skb2 = (const float*)d_in[10];
    const float* Wh   = (const float*)d_in[11];
    const float* Wv   = (const float*)d_in[12];
    float* y = (float*)d_out;

    prep_kernel<<<16, 256>>>(sq1, sq2, sk1, sk2);
    cudaFuncSetAttribute(fused_kernel, cudaFuncAttributeMaxDynamicSharedMemorySize,
                         SMEM_FLOATS * (int)sizeof(float));
    fused_kernel<<<G, T, SMEM_FLOATS * sizeof(float)>>>(
        q, k, v, sqb1, sqb2, skb1, skb2, Wh, Wv, y);
}

// round 15
// speedup vs baseline: 1.4611x; 1.0118x over previous
#include <cuda_runtime.h>
#include <math.h>

// EXACT R9 (champion @27.1us). ONE change: __nanosleep backoff in the gridbar
// poll loop. Theory: 144 blocks spin-polling one L2 line with no backoff
// starve the 144 arrival atomics on the same LTS slice; each barrier costs
// many us. Backoff lets arrivals land at ~32cyc/atomic.

#define G 144
#define T 1024

__device__ __align__(16) float g_f[2][4096];
__device__ __align__(16) float g_phi[2][4096*32];
__device__ __align__(16) float g_u[4096*32];
__device__ __align__(16) float g_Mpart[64][1024];
__device__ unsigned g_mg_ord[8];
__device__ unsigned g_m2_ord[8*32];
__device__ unsigned long long g_bar;

__device__ __forceinline__ float softplusf(float x){
    return x > 20.0f ? x : __logf(1.0f + __expf(x));
}
__device__ __forceinline__ unsigned ordf(float f){
    unsigned u = __float_as_uint(f);
    return (u & 0x80000000u) ? ~u : (u | 0x80000000u);
}
__device__ __forceinline__ float deco(unsigned k){
    return __uint_as_float((k & 0x80000000u) ? (k ^ 0x80000000u) : ~k);
}

__device__ __forceinline__ unsigned long long pk2(float a){
    unsigned long long r;
    asm("mov.b64 %0, {%1, %1};" : "=l"(r) : "f"(a));
    return r;
}
__device__ __forceinline__ void fma2(unsigned long long &acc,
                                     unsigned long long a, unsigned long long b){
    asm("fma.rn.f32x2 %0, %1, %2, %0;" : "+l"(acc) : "l"(a), "l"(b));
}
__device__ __forceinline__ void up2(unsigned long long v, float &lo, float &hi){
    asm("mov.b64 {%0, %1}, %2;" : "=f"(lo), "=f"(hi) : "l"(v));
}

__device__ __forceinline__ void gridbar(){
    __syncthreads();
    if (threadIdx.x == 0){
        __threadfence();
        unsigned long long t = atomicAdd(&g_bar, 1ULL);
        unsigned long long target = (t / G + 1ULL) * G;
        unsigned ns = 32;
        while (*((volatile unsigned long long*)&g_bar) < target){
            __nanosleep(ns);
            if (ns < 256) ns <<= 1;
        }
        __threadfence();
    }
    __syncthreads();
}

// ---- shared layout (floats) ----
// ICNN blocks:
#define O_W1   0        // 64x65
#define O_W2   4160     // 64x65
#define O_WHT  8320     // 64x32  [d][r]
#define O_X    10368    // 64x64  [t][d]
#define O_XT   14464    // 64x68  [d][t]
#define O_Z1T  18816    // 64x68
#define O_B1   23168
#define O_B2   23232
#define O_RED  23296    // 128
// u-blocks:
#define O_UWVT 0        // 64x32 [d][p]
#define O_SVT  2048     // 64x264 [d][t]
#define O_URED 18944    // 1024
#define SMEM_FLOATS 23424

__global__ void __launch_bounds__(T, 1) fused_kernel(
    const float* __restrict__ q,  const float* __restrict__ k,  const float* __restrict__ v,
    const float* __restrict__ sq1, const float* __restrict__ sqb1,
    const float* __restrict__ sq2, const float* __restrict__ sqb2,
    const float* __restrict__ sk1, const float* __restrict__ skb1,
    const float* __restrict__ sk2, const float* __restrict__ skb2,
    const float* __restrict__ Wh, const float* __restrict__ Wv,
    float* __restrict__ y)
{
    extern __shared__ __align__(16) float S[];
    const int tid = threadIdx.x;
    const int bid = blockIdx.x;

    // ============================ PHASE 1 ============================
    if (bid < 128){
        const int which = (bid >= 64);
        const float* x    = which ? k   : q;
        const float* raw1 = which ? sk1 : sq1;
        const float* raw2 = which ? sk2 : sq2;
        const float* b1   = which ? skb1: sqb1;
        const float* b2   = which ? skb2: sqb2;
        const int tb = (which ? bid - 64 : bid) * 64;
        const int h  = tb >> 9;

        float* sW1  = S + O_W1;
        float* sW2  = S + O_W2;
        float* sWhT = S + O_WHT;
        float* sx   = S + O_X;
        float* sxT  = S + O_XT;
        float* sz1T = S + O_Z1T;
        float* sb1  = S + O_B1;
        float* sb2  = S + O_B2;
        float* sred = S + O_RED;

        for (int i = tid; i < 4096; i += T){
            int j = i >> 6, d = i & 63;
            sW1[j*65 + d] = softplusf(raw1[i]);
            sW2[j*65 + d] = softplusf(raw2[i]);
        }
        for (int i = tid; i < 2048; i += T){
            int r = i >> 6, d = i & 63;
            sWhT[d*32 + r] = Wh[i];
        }
        for (int i = tid; i < 4096; i += T){
            int t = i >> 6, d = i & 63;
            float val = x[tb*64 + i];
            sx[i] = val;
            sxT[d*68 + t] = val;
        }
        if (tid < 64){ sb1[tid] = b1[tid]; sb2[tid] = b2[tid]; }
        __syncthreads();

        const int grp = tid >> 6;     // 0..15, 4 tokens each
        const int j   = tid & 63;
        const int t0  = grp * 4;

        {   // layer 1
            unsigned long long a0, a1;
            a0 = a1 = pk2(sb1[j]);
            #pragma unroll 16
            for (int d = 0; d < 64; d++){
                unsigned long long ww = pk2(sW1[j*65 + d]);
                ulonglong2 xa = *(const ulonglong2*)&sxT[d*68 + t0];
                fma2(a0, xa.x, ww); fma2(a1, xa.y, ww);
            }
            float z[4];
            up2(a0, z[0], z[1]); up2(a1, z[2], z[3]);
            #pragma unroll
            for (int i = 0; i < 4; i++) z[i] = softplusf(z[i]);
            unsigned long long s1x, s1y;
            asm("mov.b64 %0, {%1, %2};" : "=l"(s1x) : "f"(z[0]), "f"(z[1]));
            asm("mov.b64 %0, {%1, %2};" : "=l"(s1y) : "f"(z[2]), "f"(z[3]));
            ulonglong2 s1; s1.x = s1x; s1.y = s1y;
            *(ulonglong2*)&sz1T[j*68 + t0] = s1;
        }
        __syncthreads();

        {   // layer 2 + reduce over j
            unsigned long long a0, a1;
            a0 = a1 = pk2(sb2[j]);
            #pragma unroll 16
            for (int d = 0; d < 64; d++){
                unsigned long long ww = pk2(sW2[j*65 + d]);
                ulonglong2 xa = *(const ulonglong2*)&sz1T[d*68 + t0];
                fma2(a0, xa.x, ww); fma2(a1, xa.y, ww);
            }
            float cv[4];
            up2(a0, cv[0], cv[1]); up2(a1, cv[2], cv[3]);
            #pragma unroll
            for (int i = 0; i < 4; i++){
                float cc2 = softplusf(cv[i]);
                #pragma unroll
                for (int o = 16; o > 0; o >>= 1)
                    cc2 += __shfl_xor_sync(0xffffffffu, cc2, o);
                cv[i] = cc2;
            }
            if ((tid & 31) == 0){
                int w = tid >> 5;   // 0..31
                #pragma unroll
                for (int i = 0; i < 4; i++) sred[w*4 + i] = cv[i];
            }
        }
        __syncthreads();

        if (tid < 64){
            int t = tid, g2 = t >> 2, i2 = t & 3;
            float f = sred[(g2*2)*4 + i2] + sred[(g2*2 + 1)*4 + i2];
            g_f[which][tb + t] = f;
            if (which){
                float m = f;
                #pragma unroll
                for (int o = 16; o > 0; o >>= 1)
                    m = fmaxf(m, __shfl_xor_sync(0xffffffffu, m, o));
                if ((tid & 31) == 0) atomicMax(&g_mg_ord[h], ordf(m));
            }
        }

        {   // phi: thread = (token, 2 r's)
            const int pt = tid >> 4;          // 0..63
            const int r0 = (tid & 15) * 2;
            unsigned long long p01 = 0ULL;
            #pragma unroll 8
            for (int d4 = 0; d4 < 64; d4 += 4){
                float4 xq = *(const float4*)&sx[pt*64 + d4];
                { unsigned long long wp = *(const unsigned long long*)&sWhT[(d4  )*32 + r0];
                  fma2(p01, pk2(xq.x), wp); }
                { unsigned long long wp = *(const unsigned long long*)&sWhT[(d4+1)*32 + r0];
                  fma2(p01, pk2(xq.y), wp); }
                { unsigned long long wp = *(const unsigned long long*)&sWhT[(d4+2)*32 + r0];
                  fma2(p01, pk2(xq.z), wp); }
                { unsigned long long wp = *(const unsigned long long*)&sWhT[(d4+3)*32 + r0];
                  fma2(p01, pk2(xq.w), wp); }
            }
            float e0, e1;
            up2(p01, e0, e1);
            int base = (tb + pt)*32 + r0;
            g_phi[which][base + 0] = __expf(e0);
            g_phi[which][base + 1] = __expf(e1);
        }
    } else {
        // ---- u = v @ Wv.T, blocks 128..143, 256 tokens each ----
        const int ub = bid - 128;
        const int tb = ub * 256;
        const int h  = tb >> 9;
        float* sWvT = S + O_UWVT;
        float* svT  = S + O_SVT;       // [d][t] stride 264
        float* sred = S + O_URED;      // 32x32

        for (int i = tid; i < 2048; i += T){
            int r = i >> 6, d = i & 63;
            sWvT[d*32 + r] = Wv[i];
        }
        for (int i = tid; i < 16384; i += T){
            int t = i >> 6, d = i & 63;
            svT[d*264 + t] = v[tb*64 + i];
        }
        __syncthreads();

        const int p = tid & 31, tr = tid >> 5;   // 32 tr, 8 tokens each
        const int t0 = tr*8;
        unsigned long long a0=0,a1=0,a2=0,a3=0;
        #pragma unroll 8
        for (int d = 0; d < 64; d++){
            unsigned long long ww = pk2(sWvT[d*32 + p]);
            const float* row = &svT[d*264];
            ulonglong2 xa = *(const ulonglong2*)&row[t0];
            ulonglong2 xb = *(const ulonglong2*)&row[t0 + 4];
            fma2(a0, xa.x, ww); fma2(a1, xa.y, ww);
            fma2(a2, xb.x, ww); fma2(a3, xb.y, ww);
        }
        float uv[8];
        up2(a0, uv[0], uv[1]); up2(a1, uv[2], uv[3]);
        up2(a2, uv[4], uv[5]); up2(a3, uv[6], uv[7]);
        float mx = -1e30f;
        #pragma unroll
        for (int i = 0; i < 8; i++){
            g_u[(tb + t0 + i)*32 + p] = uv[i];
            mx = fmaxf(mx, uv[i]);
        }
        sred[tr*32 + p] = mx;
        __syncthreads();
        if (tid < 32){
            float m = sred[tid];
            #pragma unroll
            for (int rr = 1; rr < 32; rr++) m = fmaxf(m, sred[rr*32 + tid]);
            atomicMax(&g_m2_ord[h*32 + tid], ordf(m));
        }
    }

    gridbar();

    // ============================ PHASE 2 ============================
    if (bid < 64){
        const int h = bid >> 3, c = bid & 7;
        const int gtb = h*512 + c*64;
        float* seg = S;          // 64
        float* sm2 = S + 64;     // 32
        float* sw  = S + 96;     // 64x32
        float* spk = S + 96 + 2048; // 64x32

        float mg = deco(__ldcg(&g_mg_ord[h]));
        if (tid < 32) sm2[tid] = deco(__ldcg(&g_m2_ord[h*32 + tid]));
        if (tid >= 64 && tid < 128) seg[tid - 64] = __expf(__ldcg(&g_f[1][gtb + tid - 64]) - mg);
        __syncthreads();

        for (int i = tid; i < 2048; i += T){
            int t = i >> 5, p = i & 31;
            sw[i]  = seg[t] * __expf(__ldcg(&g_u[(gtb + t)*32 + p]) - sm2[p]);
            spk[i] = __ldcg(&g_phi[1][(gtb + t)*32 + p]);
        }
        __syncthreads();

        if (tid < 1024){
            int r = tid >> 5, p = tid & 31;
            float a = 0.f;
            #pragma unroll
            for (int t = 0; t < 64; t++) a += spk[t*32 + r] * sw[t*32 + p];
            g_Mpart[bid][tid] = a;
        }
    }

    gridbar();

    // ============================ PHASE 3 ============================
    if (bid < 128){
        const int h = bid >> 4, sc = bid & 15;
        const int s0 = h*512 + sc*32;
        float* sM  = S;          // 32x32
        float* spq = S + 1024;   // 32x32
        float* sm2 = S + 2048;   // 32
        float* sf  = S + 2080;   // 32

        if (tid < 1024){
            float a = 0.f;
            #pragma unroll
            for (int c = 0; c < 8; c++) a += __ldcg(&g_Mpart[h*8 + c][tid]);
            sM[tid] = a;
            spq[tid] = __ldcg(&g_phi[0][s0*32 + tid]);
        }
        if (tid < 32){
            sm2[tid] = deco(__ldcg(&g_m2_ord[h*32 + tid]));
            sf[tid]  = __ldcg(&g_f[0][s0 + tid]);
        }
        float mg = deco(__ldcg(&g_mg_ord[h]));
        __syncthreads();

        const float LOGS = 6.2383246250395077847f; // log(512)
        if (tid < 1024){
            int s = tid >> 5, p = tid & 31;
            float a = 0.f;
            #pragma unroll
            for (int r = 0; r < 32; r++) a += spq[s*32 + r] * sM[r*32 + p];
            y[(s0 + s)*32 + p] = sf[s] + mg + sm2[p] - LOGS + __logf(a);
        }
    }
}

extern "C" void kernel_launch(void* const* d_in, const int* in_sizes, int n_in,
                              void* d_out, int out_size){
    const float* q    = (const float*)d_in[0];
    const float* k    = (const float*)d_in[1];
    const float* v    = (const float*)d_in[2];
    const float* sq1  = (const float*)d_in[3];
    const float* sqb1 = (const float*)d_in[4];
    const float* sq2  = (const float*)d_in[5];
    const float* sqb2 = (const float*)d_in[6];
    const float* sk1  = (const float*)d_in[7];
    const float* skb1 = (const float*)d_in[8];
    const float* sk2  = (const float*)d_in[9];
    const float* skb2 = (const float*)d_in[10];
    const float* Wh   = (const float*)d_in[11];
    const float* Wv   = (const float*)d_in[12];
    float* y = (float*)d_out;

    cudaFuncSetAttribute(fused_kernel, cudaFuncAttributeMaxDynamicSharedMemorySize,
                         SMEM_FLOATS * (int)sizeof(float));
    fused_kernel<<<G, T, SMEM_FLOATS * sizeof(float)>>>(
        q, k, v, sq1, sqb1, sq2, sqb2, sk1, skb1, sk2, skb2, Wh, Wv, y);
}